// round 2
// baseline (speedup 1.0000x reference)
#include <cuda_runtime.h>
#include <cuda_bf16.h>
#include <cstdint>

#define N_NODES 4096
#define N_FEAT  1024
#define N_HID   8
#define N_HEADS 8
#define N_CLS   16
#define NCOL    64   // N_HEADS * N_HID

// ---------------- scratch (static device globals: allocation-free) ----------
__device__ float g_Wall[N_FEAT * NCOL];          // repacked W_heads [k][c]
__device__ float g_Wh  [N_NODES * NCOL];         // layer-1 per-head features
__device__ float g_fs1 [N_NODES * N_HEADS];
__device__ float g_fd1 [N_NODES * N_HEADS];
__device__ float g_H1  [N_NODES * NCOL];         // layer-1 attention output (pre-elu)
__device__ float g_Wh2 [N_NODES * N_CLS];
__device__ float g_fs2 [N_NODES];
__device__ float g_fd2 [N_NODES];
__device__ unsigned short g_nbr[(size_t)N_NODES * N_NODES]; // row-major neighbor lists
__device__ int   g_cnt [N_NODES];

// ---------------- f32x2 packed FMA helpers ----------------------------------
__device__ __forceinline__ void ffma2(unsigned long long& d,
                                      unsigned long long a,
                                      unsigned long long b) {
    asm("fma.rn.f32x2 %0, %1, %2, %0;" : "+l"(d) : "l"(a), "l"(b));
}
__device__ __forceinline__ unsigned long long dup2(float x) {
    unsigned long long r; unsigned xi = __float_as_uint(x);
    asm("mov.b64 %0, {%1, %1};" : "=l"(r) : "r"(xi));
    return r;
}
__device__ __forceinline__ float lo2(unsigned long long v) {
    unsigned a, b; asm("mov.b64 {%0, %1}, %2;" : "=r"(a), "=r"(b) : "l"(v));
    return __uint_as_float(a);
}
__device__ __forceinline__ float hi2(unsigned long long v) {
    unsigned a, b; asm("mov.b64 {%0, %1}, %2;" : "=r"(a), "=r"(b) : "l"(v));
    return __uint_as_float(b);
}

// ---------------- kernel 0: repack W_heads [8][1024][8] -> [1024][64] -------
__global__ void repack_kernel(const float* __restrict__ Wheads) {
    int idx = blockIdx.x * 1024 + threadIdx.x;   // 64 blocks x 1024 threads
    int k = idx >> 6, c = idx & 63;
    g_Wall[idx] = Wheads[((c >> 3) << 13) + (k << 3) + (c & 7)];
}

// ---------------- kernel 1: GEMM1 (x @ W_all) + per-head feature dots -------
// BM=32, BN=64, BK=32, 256 threads, 128 blocks. f32x2 accumulators.
__global__ __launch_bounds__(256) void gemm1_kernel(const float* __restrict__ X,
                                                    const float* __restrict__ a_heads) {
    __shared__ float Xs[32][34];   // transposed X tile [k][r]
    __shared__ float Ws[32][64];
    __shared__ float sAsrc[64], sAdst[64];

    int tid = threadIdx.x;
    if (tid < 64) {
        int h = tid >> 3, f = tid & 7;
        sAsrc[tid] = a_heads[h * 16 + f];
        sAdst[tid] = a_heads[h * 16 + 8 + f];
    }
    int row0 = blockIdx.x * 32;
    int ty = tid >> 4, tx = tid & 15;          // ty: 16 row-groups x2, tx: 16 col-groups x4
    unsigned long long acc00 = 0, acc01 = 0, acc10 = 0, acc11 = 0;

    const int rX = tid >> 3, cX4 = (tid & 7) * 4;
    for (int k0 = 0; k0 < N_FEAT; k0 += 32) {
        __syncthreads();
        // load X tile (32x32) transposed
        float4 xv = *(const float4*)(X + (size_t)(row0 + rX) * N_FEAT + k0 + cX4);
        Xs[cX4 + 0][rX] = xv.x; Xs[cX4 + 1][rX] = xv.y;
        Xs[cX4 + 2][rX] = xv.z; Xs[cX4 + 3][rX] = xv.w;
        // load W tile (32x64): 512 float4, 2 per thread
        {
            int q = tid;       int kr = q >> 4, c4 = (q & 15) * 4;
            *(float4*)&Ws[kr][c4] = *(const float4*)(g_Wall + (k0 + kr) * 64 + c4);
            q = tid + 256;     kr = q >> 4;     c4 = (q & 15) * 4;
            *(float4*)&Ws[kr][c4] = *(const float4*)(g_Wall + (k0 + kr) * 64 + c4);
        }
        __syncthreads();
#pragma unroll
        for (int k = 0; k < 32; k++) {
            float2 xp = *(const float2*)&Xs[k][ty * 2];
            ulonglong2 wp = *(const ulonglong2*)&Ws[k][tx * 4];  // (c0,c1),(c2,c3)
            unsigned long long x0 = dup2(xp.x), x1 = dup2(xp.y);
            ffma2(acc00, x0, wp.x); ffma2(acc01, x0, wp.y);
            ffma2(acc10, x1, wp.x); ffma2(acc11, x1, wp.y);
        }
    }
    // unpack
    float o[2][4];
    o[0][0] = lo2(acc00); o[0][1] = hi2(acc00); o[0][2] = lo2(acc01); o[0][3] = hi2(acc01);
    o[1][0] = lo2(acc10); o[1][1] = hi2(acc10); o[1][2] = lo2(acc11); o[1][3] = hi2(acc11);
#pragma unroll
    for (int rr = 0; rr < 2; rr++) {
        int r = row0 + ty * 2 + rr;
        *(float4*)(g_Wh + (size_t)r * NCOL + tx * 4) =
            make_float4(o[rr][0], o[rr][1], o[rr][2], o[rr][3]);
        // per-head feature dots: this thread's 4 cols are within head tx/2
        float fsp = 0.f, fdp = 0.f;
#pragma unroll
        for (int i = 0; i < 4; i++) {
            fsp += o[rr][i] * sAsrc[tx * 4 + i];
            fdp += o[rr][i] * sAdst[tx * 4 + i];
        }
        fsp += __shfl_xor_sync(0xffffffffu, fsp, 1);
        fdp += __shfl_xor_sync(0xffffffffu, fdp, 1);
        if ((tx & 1) == 0) {
            int h = tx >> 1;
            g_fs1[r * N_HEADS + h] = fsp;
            g_fd1[r * N_HEADS + h] = fdp;
        }
    }
}

// ---------------- kernel 2: neighbor-list build + layer-1 attention ---------
// one block (256 thr) per row. Deterministic compaction via prefix scan.
__global__ __launch_bounds__(256) void attn1_kernel(const float* __restrict__ adj) {
    __shared__ unsigned short sList[4096];
    __shared__ int sWs[9];
    __shared__ float sfs[8];

    int row = blockIdx.x, tid = threadIdx.x;
    if (tid < 8) sfs[tid] = g_fs1[row * N_HEADS + tid];

    const float* arow = adj + (size_t)row * N_NODES;
    int base = tid * 16;
    unsigned mask = 0;
#pragma unroll
    for (int q = 0; q < 4; q++) {
        float4 v = *(const float4*)(arow + base + q * 4);
        if (v.x > 0.f) mask |= 1u << (q * 4 + 0);
        if (v.y > 0.f) mask |= 1u << (q * 4 + 1);
        if (v.z > 0.f) mask |= 1u << (q * 4 + 2);
        if (v.w > 0.f) mask |= 1u << (q * 4 + 3);
    }
    int c = __popc(mask);
    int lane = tid & 31, wid = tid >> 5;
    int v = c;
#pragma unroll
    for (int off = 1; off < 32; off <<= 1) {
        int n = __shfl_up_sync(0xffffffffu, v, off);
        if (lane >= off) v += n;
    }
    if (lane == 31) sWs[wid] = v;
    __syncthreads();
    if (tid == 0) {
        int a = 0;
#pragma unroll
        for (int w = 0; w < 8; w++) { int t = sWs[w]; sWs[w] = a; a += t; }
        sWs[8] = a;
    }
    __syncthreads();
    int pos = sWs[wid] + v - c;
#pragma unroll
    for (int u = 0; u < 16; u++)
        if (mask & (1u << u)) sList[pos++] = (unsigned short)(base + u);
    __syncthreads();
    int cnt = sWs[8];
    if (tid == 0) g_cnt[row] = cnt;
    for (int t = tid; t < cnt; t += 256)
        g_nbr[(size_t)row * N_NODES + t] = sList[t];

    // phase 2: warp 0 computes all 8 heads; lane l owns cols l and l+32
    if (tid < 32) {
        int l = tid;
        int h0 = l >> 3, h1 = 4 + (l >> 3);
        float fsa = sfs[h0], fsb = sfs[h1];
        float acc0 = 0.f, acc1 = 0.f, s0 = 0.f, s1 = 0.f;
        for (int e = 0; e < cnt; e++) {
            int j = sList[e];
            float e0 = fsa + __ldg(&g_fd1[j * N_HEADS + h0]);
            float e1 = fsb + __ldg(&g_fd1[j * N_HEADS + h1]);
            e0 = e0 > 0.f ? e0 : 0.2f * e0;
            e1 = e1 > 0.f ? e1 : 0.2f * e1;
            float w0 = __expf(e0), w1 = __expf(e1);
            acc0 += w0 * __ldg(&g_Wh[(size_t)j * NCOL + l]);
            acc1 += w1 * __ldg(&g_Wh[(size_t)j * NCOL + 32 + l]);
            if ((l & 7) == 0) { s0 += w0; s1 += w1; }
        }
        int srcl = (l >> 3) << 3;
        float S0 = __shfl_sync(0xffffffffu, s0, srcl);
        float S1 = __shfl_sync(0xffffffffu, s1, srcl);
        g_H1[(size_t)row * NCOL + l]      = acc0 / S0;
        g_H1[(size_t)row * NCOL + 32 + l] = acc1 / S1;
    }
}

// ---------------- kernel 3: elu + layer-2 GEMM (64x16) + feature dots -------
// block: 256 threads = 16 rows x 16 classes; grid 256
__global__ __launch_bounds__(256) void prep2_kernel(const float* __restrict__ Wf,
                                                    const float* __restrict__ af) {
    __shared__ float sW[64 * 16];
    __shared__ float sA[32];
    __shared__ float sH[16][64];
    int tid = threadIdx.x;
    for (int t = tid; t < 1024; t += 256) sW[t] = Wf[t];
    if (tid < 32) sA[tid] = af[tid];
    int row0 = blockIdx.x * 16;
    // stage 16 elu'd rows into shared: 4 rows per pass
    {
        int rloc0 = tid >> 6, kk = tid & 63;
#pragma unroll
        for (int p = 0; p < 4; p++) {
            int rl = p * 4 + rloc0;
            float hv = g_H1[(size_t)(row0 + rl) * NCOL + kk];
            sH[rl][kk] = hv > 0.f ? hv : expm1f(hv);
        }
    }
    __syncthreads();
    int rl = tid >> 4, cc = tid & 15;
    float acc = 0.f;
#pragma unroll
    for (int k = 0; k < 64; k++) acc += sH[rl][k] * sW[k * 16 + cc];
    int r = row0 + rl;
    g_Wh2[r * N_CLS + cc] = acc;
    float fsp = acc * sA[cc], fdp = acc * sA[16 + cc];
#pragma unroll
    for (int off = 8; off; off >>= 1) {
        fsp += __shfl_down_sync(0xffffffffu, fsp, off, 16);
        fdp += __shfl_down_sync(0xffffffffu, fdp, off, 16);
    }
    if (cc == 0) { g_fs2[r] = fsp; g_fd2[r] = fdp; }
}

// ---------------- kernel 4: layer-2 attention + log_softmax -----------------
// warp per row; grid 512 x 256 threads
__global__ __launch_bounds__(256) void attn2_kernel(float* __restrict__ out) {
    int tid = threadIdx.x, lane = tid & 31;
    int row = blockIdx.x * 8 + (tid >> 5);
    int cnt = g_cnt[row];
    float fs = g_fs2[row];
    const unsigned short* nb = g_nbr + (size_t)row * N_NODES;
    float acc = 0.f, s = 0.f;
    for (int e = 0; e < cnt; e++) {
        int j = nb[e];
        float ev = fs + __ldg(&g_fd2[j]);
        ev = ev > 0.f ? ev : 0.2f * ev;
        float w = __expf(ev);
        s += w;
        if (lane < 16) acc += w * __ldg(&g_Wh2[j * N_CLS + lane]);
    }
    if (lane < 16) {
        float o = acc / s;
        float m = o;
#pragma unroll
        for (int off = 8; off; off >>= 1)
            m = fmaxf(m, __shfl_xor_sync(0x0000ffffu, m, off, 16));
        float ex = __expf(o - m), sum = ex;
#pragma unroll
        for (int off = 8; off; off >>= 1)
            sum += __shfl_xor_sync(0x0000ffffu, sum, off, 16);
        out[row * N_CLS + lane] = o - m - __logf(sum);
    }
}

// ---------------- launch ----------------------------------------------------
extern "C" void kernel_launch(void* const* d_in, const int* in_sizes, int n_in,
                              void* d_out, int out_size) {
    (void)in_sizes; (void)n_in; (void)out_size;
    const float* x       = (const float*)d_in[0];
    const float* adj     = (const float*)d_in[1];
    const float* W_heads = (const float*)d_in[2];
    const float* a_heads = (const float*)d_in[3];
    const float* W_final = (const float*)d_in[4];
    const float* a_final = (const float*)d_in[5];
    float* out = (float*)d_out;

    repack_kernel<<<64, 1024>>>(W_heads);
    gemm1_kernel<<<128, 256>>>(x, a_heads);
    attn1_kernel<<<N_NODES, 256>>>(adj);
    prep2_kernel<<<256, 256>>>(W_final, a_final);
    attn2_kernel<<<512, 256>>>(out);
}

// round 3
// speedup vs baseline: 1.4142x; 1.4142x over previous
#include <cuda_runtime.h>
#include <cuda_bf16.h>
#include <cstdint>

#define N_NODES 4096
#define N_FEAT  1024
#define N_HID   8
#define N_HEADS 8
#define N_CLS   16
#define NCOL    64   // N_HEADS * N_HID
#define KSPLIT  4

// ---------------- scratch (static device globals: allocation-free) ----------
__device__ float g_Wall[N_FEAT * NCOL];            // repacked W_heads [k][c]
__device__ float g_part[KSPLIT][N_NODES * NCOL];   // split-K partials
__device__ float g_Wh  [N_NODES * NCOL];
__device__ float g_fs1 [N_NODES * N_HEADS];
__device__ float g_fd1 [N_NODES * N_HEADS];
__device__ float g_Wh2 [N_NODES * N_CLS];
__device__ float g_fs2 [N_NODES];
__device__ float g_fd2 [N_NODES];
__device__ unsigned short g_nbr[(size_t)N_NODES * N_NODES];
__device__ int   g_cnt [N_NODES];

// ---------------- f32x2 packed FMA helpers ----------------------------------
__device__ __forceinline__ void ffma2(unsigned long long& d,
                                      unsigned long long a,
                                      unsigned long long b) {
    asm("fma.rn.f32x2 %0, %1, %2, %0;" : "+l"(d) : "l"(a), "l"(b));
}
__device__ __forceinline__ unsigned long long dup2(float x) {
    unsigned long long r; unsigned xi = __float_as_uint(x);
    asm("mov.b64 %0, {%1, %1};" : "=l"(r) : "r"(xi));
    return r;
}
__device__ __forceinline__ float lo2(unsigned long long v) {
    unsigned a, b; asm("mov.b64 {%0, %1}, %2;" : "=r"(a), "=r"(b) : "l"(v));
    return __uint_as_float(a);
}
__device__ __forceinline__ float hi2(unsigned long long v) {
    unsigned a, b; asm("mov.b64 {%0, %1}, %2;" : "=r"(a), "=r"(b) : "l"(v));
    return __uint_as_float(b);
}

// ---------------- kernel 0: repack W_heads [8][1024][8] -> [1024][64] -------
__global__ void repack_kernel(const float* __restrict__ Wheads) {
    int idx = blockIdx.x * 1024 + threadIdx.x;
    int k = idx >> 6, c = idx & 63;
    g_Wall[idx] = Wheads[((c >> 3) << 13) + (k << 3) + (c & 7)];
}

// ---------------- kernel 1: GEMM1, split-K, double-buffered ------------------
// grid (64, 4): 64 row-tiles of 64 rows, 4 K-splits of 256. 128 threads.
// Thread tile: 8 rows x 4 cols (cols as 2 x f32x2).
__global__ __launch_bounds__(128) void gemm1_kernel(const float* __restrict__ X) {
    __shared__ float Xs[2][32][72];   // [k][row], padded
    __shared__ float Ws[2][32][64];

    const int tid = threadIdx.x;
    const int tx = tid & 15;          // col group (4 cols)
    const int ty = tid >> 4;          // row group (8 rows)
    const int row0 = blockIdx.x * 64;
    const int kbase = blockIdx.y * 256;

    // loader indices: 512 float4 per tile for X and W, 4 per thread
    // X: f -> row = f>>3 (0..63), kq = f&7 ;  W: f -> kr = f>>4, c4 = (f&15)*4
    float4 xr[4], wr[4];

    auto ldg_tile = [&](int k0) {
#pragma unroll
        for (int i = 0; i < 4; i++) {
            int f = tid + i * 128;
            int xrow = f >> 3, kq = f & 7;
            xr[i] = *(const float4*)(X + (size_t)(row0 + xrow) * N_FEAT + k0 + kq * 4);
            int kr = f >> 4, c4 = (f & 15) * 4;
            wr[i] = *(const float4*)(g_Wall + (k0 + kr) * 64 + c4);
        }
    };
    auto sts_tile = [&](int b) {
#pragma unroll
        for (int i = 0; i < 4; i++) {
            int f = tid + i * 128;
            int xrow = f >> 3, kq = f & 7;
            Xs[b][kq * 4 + 0][xrow] = xr[i].x;
            Xs[b][kq * 4 + 1][xrow] = xr[i].y;
            Xs[b][kq * 4 + 2][xrow] = xr[i].z;
            Xs[b][kq * 4 + 3][xrow] = xr[i].w;
            int kr = f >> 4, c4 = (f & 15) * 4;
            *(float4*)&Ws[b][kr][c4] = wr[i];
        }
    };

    unsigned long long acc[8][2];
#pragma unroll
    for (int r = 0; r < 8; r++) { acc[r][0] = 0ull; acc[r][1] = 0ull; }

    ldg_tile(kbase);
    sts_tile(0);
    __syncthreads();

#pragma unroll 1
    for (int t = 0; t < 8; t++) {
        int cur = t & 1;
        if (t < 7) ldg_tile(kbase + (t + 1) * 32);
#pragma unroll
        for (int k = 0; k < 32; k++) {
            float4 xlo = *(const float4*)&Xs[cur][k][ty * 8];
            float4 xhi = *(const float4*)&Xs[cur][k][ty * 8 + 4];
            ulonglong2 wv = *(const ulonglong2*)&Ws[cur][k][tx * 4];
            unsigned long long xv;
            xv = dup2(xlo.x); ffma2(acc[0][0], xv, wv.x); ffma2(acc[0][1], xv, wv.y);
            xv = dup2(xlo.y); ffma2(acc[1][0], xv, wv.x); ffma2(acc[1][1], xv, wv.y);
            xv = dup2(xlo.z); ffma2(acc[2][0], xv, wv.x); ffma2(acc[2][1], xv, wv.y);
            xv = dup2(xlo.w); ffma2(acc[3][0], xv, wv.x); ffma2(acc[3][1], xv, wv.y);
            xv = dup2(xhi.x); ffma2(acc[4][0], xv, wv.x); ffma2(acc[4][1], xv, wv.y);
            xv = dup2(xhi.y); ffma2(acc[5][0], xv, wv.x); ffma2(acc[5][1], xv, wv.y);
            xv = dup2(xhi.z); ffma2(acc[6][0], xv, wv.x); ffma2(acc[6][1], xv, wv.y);
            xv = dup2(xhi.w); ffma2(acc[7][0], xv, wv.x); ffma2(acc[7][1], xv, wv.y);
        }
        if (t < 7) {
            __syncthreads();
            sts_tile(cur ^ 1);
            __syncthreads();
        }
    }

    float* dst = g_part[blockIdx.y];
#pragma unroll
    for (int r = 0; r < 8; r++) {
        int row = row0 + ty * 8 + r;
        *(float4*)(dst + (size_t)row * NCOL + tx * 4) =
            make_float4(lo2(acc[r][0]), hi2(acc[r][0]), lo2(acc[r][1]), hi2(acc[r][1]));
    }
}

// ---------------- kernel 2: split-K reduce + per-head feature dots -----------
// grid 1024 x 256 thr; thread -> one (row, col)
__global__ __launch_bounds__(256) void reduce_kernel(const float* __restrict__ a_heads) {
    __shared__ float sAsrc[64], sAdst[64];
    int tid = threadIdx.x;
    if (tid < 64) {
        int h = tid >> 3, f = tid & 7;
        sAsrc[tid] = a_heads[h * 16 + f];
        sAdst[tid] = a_heads[h * 16 + 8 + f];
    }
    __syncthreads();
    int idx = blockIdx.x * 256 + tid;
    int c = idx & 63;
    float s = g_part[0][idx] + g_part[1][idx] + g_part[2][idx] + g_part[3][idx];
    g_Wh[idx] = s;
    float fsp = s * sAsrc[c], fdp = s * sAdst[c];
#pragma unroll
    for (int off = 1; off < 8; off <<= 1) {
        fsp += __shfl_xor_sync(0xffffffffu, fsp, off);
        fdp += __shfl_xor_sync(0xffffffffu, fdp, off);
    }
    if ((c & 7) == 0) {
        int row = idx >> 6, h = c >> 3;
        g_fs1[row * N_HEADS + h] = fsp;
        g_fd1[row * N_HEADS + h] = fdp;
    }
}

// ---------------- kernel 3: nbr build + layer-1 attn + elu + W2 + dots ------
__global__ __launch_bounds__(256) void attn1_kernel(const float* __restrict__ adj,
                                                    const float* __restrict__ Wf,
                                                    const float* __restrict__ af) {
    __shared__ unsigned short sList[4096];
    __shared__ int sWs[9];
    __shared__ float sfs[8];
    __shared__ float sH[64];
    __shared__ float sWf[64 * 16];
    __shared__ float sAf[32];

    int row = blockIdx.x, tid = threadIdx.x;
    if (tid < 8) sfs[tid] = g_fs1[row * N_HEADS + tid];
    for (int t = tid; t < 1024; t += 256) sWf[t] = Wf[t];
    if (tid < 32) sAf[tid] = af[tid];

    // ---- phase 1: adjacency scan + deterministic compaction
    const float* arow = adj + (size_t)row * N_NODES;
    int base = tid * 16;
    unsigned mask = 0;
#pragma unroll
    for (int q = 0; q < 4; q++) {
        float4 v = *(const float4*)(arow + base + q * 4);
        if (v.x > 0.f) mask |= 1u << (q * 4 + 0);
        if (v.y > 0.f) mask |= 1u << (q * 4 + 1);
        if (v.z > 0.f) mask |= 1u << (q * 4 + 2);
        if (v.w > 0.f) mask |= 1u << (q * 4 + 3);
    }
    int c = __popc(mask);
    int lane = tid & 31, wid = tid >> 5;
    int v = c;
#pragma unroll
    for (int off = 1; off < 32; off <<= 1) {
        int n = __shfl_up_sync(0xffffffffu, v, off);
        if (lane >= off) v += n;
    }
    if (lane == 31) sWs[wid] = v;
    __syncthreads();
    if (tid == 0) {
        int a = 0;
#pragma unroll
        for (int w = 0; w < 8; w++) { int t = sWs[w]; sWs[w] = a; a += t; }
        sWs[8] = a;
    }
    __syncthreads();
    int pos = sWs[wid] + v - c;
#pragma unroll
    for (int u = 0; u < 16; u++)
        if (mask & (1u << u)) sList[pos++] = (unsigned short)(base + u);
    __syncthreads();
    int cnt = sWs[8];
    if (tid == 0) g_cnt[row] = cnt;
    for (int t = tid; t < cnt; t += 256)
        g_nbr[(size_t)row * N_NODES + t] = sList[t];

    // ---- phase 2: attention, 2 warps (warp w -> cols w*32+l, heads w*4+(l>>3))
    if (tid < 64) {
        int w = tid >> 5, l = tid & 31;
        int h = w * 4 + (l >> 3);
        float fsa = sfs[h];
        float acc = 0.f, ssum = 0.f;
        for (int e = 0; e < cnt; e++) {
            int j = sList[e];
            float ev = fsa + __ldg(&g_fd1[j * N_HEADS + h]);
            ev = ev > 0.f ? ev : 0.2f * ev;
            float wgt = __expf(ev);
            acc += wgt * __ldg(&g_Wh[(size_t)j * NCOL + w * 32 + l]);
            if ((l & 7) == 0) ssum += wgt;
        }
        float S = __shfl_sync(0xffffffffu, ssum, (l >> 3) << 3);
        float h1 = acc / S;
        sH[w * 32 + l] = h1 > 0.f ? h1 : expm1f(h1);   // elu fused
    }
    __syncthreads();

    // ---- phase 3: layer-2 projection (64x16) + feature dots (one warp)
    if (tid < 32) {
        int half = tid >> 4, cc = tid & 15;
        float acc2 = 0.f;
#pragma unroll
        for (int k = 0; k < 32; k++) {
            int kk = half * 32 + k;
            acc2 += sH[kk] * sWf[kk * 16 + cc];
        }
        acc2 += __shfl_xor_sync(0xffffffffu, acc2, 16);
        float fsp = acc2 * sAf[cc], fdp = acc2 * sAf[16 + cc];
#pragma unroll
        for (int off = 1; off < 16; off <<= 1) {
            fsp += __shfl_xor_sync(0xffffffffu, fsp, off);
            fdp += __shfl_xor_sync(0xffffffffu, fdp, off);
        }
        if (tid < 16) g_Wh2[row * N_CLS + cc] = acc2;
        if (tid == 0) { g_fs2[row] = fsp; g_fd2[row] = fdp; }
    }
}

// ---------------- kernel 4: layer-2 attention + log_softmax -----------------
// warp per row, 2 edges per iteration via half-warps
__global__ __launch_bounds__(256) void attn2_kernel(float* __restrict__ out) {
    int tid = threadIdx.x, lane = tid & 31;
    int row = blockIdx.x * 8 + (tid >> 5);
    int sub = lane >> 4, cc = lane & 15;
    int cnt = g_cnt[row];
    float fs = g_fs2[row];
    const unsigned short* nb = g_nbr + (size_t)row * N_NODES;
    float acc = 0.f, s = 0.f;
    for (int e = 0; e < cnt; e += 2) {
        int idx = e + sub;
        bool ok = idx < cnt;
        int j = nb[ok ? idx : cnt - 1];
        float ev = fs + __ldg(&g_fd2[j]);
        ev = ev > 0.f ? ev : 0.2f * ev;
        float w = ok ? __expf(ev) : 0.f;
        acc += w * __ldg(&g_Wh2[j * N_CLS + cc]);
        if (cc == 0) s += w;
    }
    acc += __shfl_xor_sync(0xffffffffu, acc, 16);
    s += __shfl_xor_sync(0xffffffffu, s, 16);
    s = __shfl_sync(0xffffffffu, s, 0);
    if (lane < 16) {
        float o = acc / s;
        float m = o;
#pragma unroll
        for (int off = 8; off; off >>= 1)
            m = fmaxf(m, __shfl_xor_sync(0x0000ffffu, m, off, 16));
        float ex = __expf(o - m), sum = ex;
#pragma unroll
        for (int off = 8; off; off >>= 1)
            sum += __shfl_xor_sync(0x0000ffffu, sum, off, 16);
        out[row * N_CLS + lane] = o - m - __logf(sum);
    }
}

// ---------------- launch ----------------------------------------------------
extern "C" void kernel_launch(void* const* d_in, const int* in_sizes, int n_in,
                              void* d_out, int out_size) {
    (void)in_sizes; (void)n_in; (void)out_size;
    const float* x       = (const float*)d_in[0];
    const float* adj     = (const float*)d_in[1];
    const float* W_heads = (const float*)d_in[2];
    const float* a_heads = (const float*)d_in[3];
    const float* W_final = (const float*)d_in[4];
    const float* a_final = (const float*)d_in[5];
    float* out = (float*)d_out;

    repack_kernel<<<64, 1024>>>(W_heads);
    gemm1_kernel<<<dim3(64, 4), 128>>>(x);
    reduce_kernel<<<1024, 256>>>(a_heads);
    attn1_kernel<<<N_NODES, 256>>>(adj, W_final, a_final);
    attn2_kernel<<<512, 256>>>(out);
}

// round 4
// speedup vs baseline: 1.5635x; 1.1056x over previous
#include <cuda_runtime.h>
#include <cuda_bf16.h>
#include <cstdint>

#define N_NODES 4096
#define N_FEAT  1024
#define N_HID   8
#define N_HEADS 8
#define N_CLS   16
#define NCOL    64   // N_HEADS * N_HID
#define KSPLIT  4

// ---------------- scratch (static device globals: allocation-free) ----------
__device__ float g_Wall[N_FEAT * NCOL];            // repacked W_heads [k][c]
__device__ float g_part[KSPLIT][N_NODES * NCOL];   // split-K partials
__device__ float g_Wh  [N_NODES * NCOL];
__device__ float g_fs1 [N_NODES * N_HEADS];
__device__ float g_fd1 [N_NODES * N_HEADS];
__device__ float g_Wh2 [N_NODES * N_CLS];
__device__ float g_fs2 [N_NODES];
__device__ float g_fd2 [N_NODES];
__device__ unsigned short g_nbr[(size_t)N_NODES * N_NODES];
__device__ int   g_cnt [N_NODES];

// ---------------- f32x2 packed FMA helpers ----------------------------------
__device__ __forceinline__ void ffma2(unsigned long long& d,
                                      unsigned long long a,
                                      unsigned long long b) {
    asm("fma.rn.f32x2 %0, %1, %2, %0;" : "+l"(d) : "l"(a), "l"(b));
}
__device__ __forceinline__ unsigned long long dup2(float x) {
    unsigned long long r; unsigned xi = __float_as_uint(x);
    asm("mov.b64 %0, {%1, %1};" : "=l"(r) : "r"(xi));
    return r;
}
__device__ __forceinline__ float lo2(unsigned long long v) {
    unsigned a, b; asm("mov.b64 {%0, %1}, %2;" : "=r"(a), "=r"(b) : "l"(v));
    return __uint_as_float(a);
}
__device__ __forceinline__ float hi2(unsigned long long v) {
    unsigned a, b; asm("mov.b64 {%0, %1}, %2;" : "=r"(a), "=r"(b) : "l"(v));
    return __uint_as_float(b);
}

// ---------------- kernel 0: repack W_heads [8][1024][8] -> [1024][64] -------
__global__ void repack_kernel(const float* __restrict__ Wheads) {
    int idx = blockIdx.x * 1024 + threadIdx.x;
    int k = idx >> 6, c = idx & 63;
    g_Wall[idx] = Wheads[((c >> 3) << 13) + (k << 3) + (c & 7)];
}

// ---------------- kernel 1: GEMM1, split-K, double-buffered ------------------
__global__ __launch_bounds__(128) void gemm1_kernel(const float* __restrict__ X) {
    __shared__ float Xs[2][32][72];   // [k][row], padded
    __shared__ float Ws[2][32][64];

    const int tid = threadIdx.x;
    const int tx = tid & 15;
    const int ty = tid >> 4;
    const int row0 = blockIdx.x * 64;
    const int kbase = blockIdx.y * 256;

    float4 xr[4], wr[4];

    auto ldg_tile = [&](int k0) {
#pragma unroll
        for (int i = 0; i < 4; i++) {
            int f = tid + i * 128;
            int xrow = f >> 3, kq = f & 7;
            xr[i] = *(const float4*)(X + (size_t)(row0 + xrow) * N_FEAT + k0 + kq * 4);
            int kr = f >> 4, c4 = (f & 15) * 4;
            wr[i] = *(const float4*)(g_Wall + (k0 + kr) * 64 + c4);
        }
    };
    auto sts_tile = [&](int b) {
#pragma unroll
        for (int i = 0; i < 4; i++) {
            int f = tid + i * 128;
            int xrow = f >> 3, kq = f & 7;
            Xs[b][kq * 4 + 0][xrow] = xr[i].x;
            Xs[b][kq * 4 + 1][xrow] = xr[i].y;
            Xs[b][kq * 4 + 2][xrow] = xr[i].z;
            Xs[b][kq * 4 + 3][xrow] = xr[i].w;
            int kr = f >> 4, c4 = (f & 15) * 4;
            *(float4*)&Ws[b][kr][c4] = wr[i];
        }
    };

    unsigned long long acc[8][2];
#pragma unroll
    for (int r = 0; r < 8; r++) { acc[r][0] = 0ull; acc[r][1] = 0ull; }

    ldg_tile(kbase);
    sts_tile(0);
    __syncthreads();

#pragma unroll 1
    for (int t = 0; t < 8; t++) {
        int cur = t & 1;
        if (t < 7) ldg_tile(kbase + (t + 1) * 32);
#pragma unroll
        for (int k = 0; k < 32; k++) {
            float4 xlo = *(const float4*)&Xs[cur][k][ty * 8];
            float4 xhi = *(const float4*)&Xs[cur][k][ty * 8 + 4];
            ulonglong2 wv = *(const ulonglong2*)&Ws[cur][k][tx * 4];
            unsigned long long xv;
            xv = dup2(xlo.x); ffma2(acc[0][0], xv, wv.x); ffma2(acc[0][1], xv, wv.y);
            xv = dup2(xlo.y); ffma2(acc[1][0], xv, wv.x); ffma2(acc[1][1], xv, wv.y);
            xv = dup2(xlo.z); ffma2(acc[2][0], xv, wv.x); ffma2(acc[2][1], xv, wv.y);
            xv = dup2(xlo.w); ffma2(acc[3][0], xv, wv.x); ffma2(acc[3][1], xv, wv.y);
            xv = dup2(xhi.x); ffma2(acc[4][0], xv, wv.x); ffma2(acc[4][1], xv, wv.y);
            xv = dup2(xhi.y); ffma2(acc[5][0], xv, wv.x); ffma2(acc[5][1], xv, wv.y);
            xv = dup2(xhi.z); ffma2(acc[6][0], xv, wv.x); ffma2(acc[6][1], xv, wv.y);
            xv = dup2(xhi.w); ffma2(acc[7][0], xv, wv.x); ffma2(acc[7][1], xv, wv.y);
        }
        if (t < 7) {
            __syncthreads();
            sts_tile(cur ^ 1);
            __syncthreads();
        }
    }

    float* dst = g_part[blockIdx.y];
#pragma unroll
    for (int r = 0; r < 8; r++) {
        int row = row0 + ty * 8 + r;
        *(float4*)(dst + (size_t)row * NCOL + tx * 4) =
            make_float4(lo2(acc[r][0]), hi2(acc[r][0]), lo2(acc[r][1]), hi2(acc[r][1]));
    }
}

// ---------------- kernel 2: split-K reduce + per-head feature dots -----------
__global__ __launch_bounds__(256) void reduce_kernel(const float* __restrict__ a_heads) {
    __shared__ float sAsrc[64], sAdst[64];
    int tid = threadIdx.x;
    if (tid < 64) {
        int h = tid >> 3, f = tid & 7;
        sAsrc[tid] = a_heads[h * 16 + f];
        sAdst[tid] = a_heads[h * 16 + 8 + f];
    }
    __syncthreads();
    int idx = blockIdx.x * 256 + tid;
    int c = idx & 63;
    float s = g_part[0][idx] + g_part[1][idx] + g_part[2][idx] + g_part[3][idx];
    g_Wh[idx] = s;
    float fsp = s * sAsrc[c], fdp = s * sAdst[c];
#pragma unroll
    for (int off = 1; off < 8; off <<= 1) {
        fsp += __shfl_xor_sync(0xffffffffu, fsp, off);
        fdp += __shfl_xor_sync(0xffffffffu, fdp, off);
    }
    if ((c & 7) == 0) {
        int row = idx >> 6, h = c >> 3;
        g_fs1[row * N_HEADS + h] = fsp;
        g_fd1[row * N_HEADS + h] = fdp;
    }
}

// ---------------- kernel 3: nbr build + layer-1 attn + elu + W2 + dots ------
__global__ __launch_bounds__(256) void attn1_kernel(const float* __restrict__ adj,
                                                    const float* __restrict__ Wf,
                                                    const float* __restrict__ af) {
    __shared__ unsigned short sList[4096];
    __shared__ int sWs[9];
    __shared__ float sfs[8];
    __shared__ float sH[64];
    __shared__ float sWf[64 * 16];
    __shared__ float sAf[32];
    __shared__ float sAcc[4][64];
    __shared__ float sS[4][8];

    int row = blockIdx.x, tid = threadIdx.x;
    if (tid < 8) sfs[tid] = g_fs1[row * N_HEADS + tid];
    for (int t = tid; t < 1024; t += 256) sWf[t] = Wf[t];
    if (tid < 32) sAf[tid] = af[tid];

    // ---- phase 1: adjacency scan + deterministic compaction
    const float* arow = adj + (size_t)row * N_NODES;
    int base = tid * 16;
    unsigned mask = 0;
#pragma unroll
    for (int q = 0; q < 4; q++) {
        float4 v = *(const float4*)(arow + base + q * 4);
        if (v.x > 0.f) mask |= 1u << (q * 4 + 0);
        if (v.y > 0.f) mask |= 1u << (q * 4 + 1);
        if (v.z > 0.f) mask |= 1u << (q * 4 + 2);
        if (v.w > 0.f) mask |= 1u << (q * 4 + 3);
    }
    int c = __popc(mask);
    int lane = tid & 31, wid = tid >> 5;
    int v = c;
#pragma unroll
    for (int off = 1; off < 32; off <<= 1) {
        int n = __shfl_up_sync(0xffffffffu, v, off);
        if (lane >= off) v += n;
    }
    if (lane == 31) sWs[wid] = v;
    __syncthreads();
    if (tid == 0) {
        int a = 0;
#pragma unroll
        for (int w = 0; w < 8; w++) { int t = sWs[w]; sWs[w] = a; a += t; }
        sWs[8] = a;
    }
    __syncthreads();
    int pos = sWs[wid] + v - c;
#pragma unroll
    for (int u = 0; u < 16; u++)
        if (mask & (1u << u)) sList[pos++] = (unsigned short)(base + u);
    __syncthreads();
    int cnt = sWs[8];
    if (tid == 0) g_cnt[row] = cnt;
    for (int t = tid; t < cnt; t += 256)
        g_nbr[(size_t)row * N_NODES + t] = sList[t];

    // ---- phase 2: attention; 4 edge-groups x 64 cols (all 256 threads)
    {
        int g = tid >> 6, l = tid & 63;
        int h = l >> 3;
        float fsa = sfs[h];
        float acc = 0.f, ssum = 0.f;
        for (int e = g; e < cnt; e += 4) {
            int j = sList[e];
            float ev = fsa + __ldg(&g_fd1[j * N_HEADS + h]);
            ev = ev > 0.f ? ev : 0.2f * ev;
            float wgt = __expf(ev);
            acc += wgt * __ldg(&g_Wh[(size_t)j * NCOL + l]);
            if ((l & 7) == 0) ssum += wgt;
        }
        sAcc[g][l] = acc;
        if ((l & 7) == 0) sS[g][h] = ssum;
    }
    __syncthreads();
    if (tid < 64) {
        int l = tid, h = l >> 3;
        float a = sAcc[0][l] + sAcc[1][l] + sAcc[2][l] + sAcc[3][l];
        float S = sS[0][h] + sS[1][h] + sS[2][h] + sS[3][h];
        float h1 = a / S;
        sH[l] = h1 > 0.f ? h1 : expm1f(h1);   // elu fused
    }
    __syncthreads();

    // ---- phase 3: layer-2 projection (64x16) + feature dots (one warp)
    if (tid < 32) {
        int half = tid >> 4, cc = tid & 15;
        float acc2 = 0.f;
#pragma unroll
        for (int k = 0; k < 32; k++) {
            int kk = half * 32 + k;
            acc2 += sH[kk] * sWf[kk * 16 + cc];
        }
        acc2 += __shfl_xor_sync(0xffffffffu, acc2, 16);
        float fsp = acc2 * sAf[cc], fdp = acc2 * sAf[16 + cc];
#pragma unroll
        for (int off = 1; off < 16; off <<= 1) {
            fsp += __shfl_xor_sync(0xffffffffu, fsp, off);
            fdp += __shfl_xor_sync(0xffffffffu, fdp, off);
        }
        if (tid < 16) g_Wh2[row * N_CLS + cc] = acc2;
        if (tid == 0) { g_fs2[row] = fsp; g_fd2[row] = fdp; }
    }
}

// ---------------- kernel 4: layer-2 attention + log_softmax -----------------
// 4 rows/block, 64 threads per row = 4 edge-subgroups x 16 classes
__global__ __launch_bounds__(256) void attn2_kernel(float* __restrict__ out) {
    __shared__ float rAcc[4][4][16];
    __shared__ float rS[4][4];

    int tid = threadIdx.x;
    int rl = tid >> 6;               // row-local 0..3
    int t64 = tid & 63;
    int sub = t64 >> 4, cc = t64 & 15;
    int row = blockIdx.x * 4 + rl;
    int cnt = g_cnt[row];
    float fs = g_fs2[row];
    const unsigned short* nb = g_nbr + (size_t)row * N_NODES;
    float acc = 0.f, s = 0.f;
    for (int e = sub; e < cnt; e += 4) {
        int j = nb[e];
        float ev = fs + __ldg(&g_fd2[j]);
        ev = ev > 0.f ? ev : 0.2f * ev;
        float w = __expf(ev);
        acc += w * __ldg(&g_Wh2[j * N_CLS + cc]);
        if (cc == 0) s += w;
    }
    rAcc[rl][sub][cc] = acc;
    if (cc == 0) rS[rl][sub] = s;
    __syncthreads();

    if (tid < 64) {
        int rr = tid >> 4, c2 = tid & 15;   // 16 lanes per row, warp-aligned
        float a = rAcc[rr][0][c2] + rAcc[rr][1][c2] + rAcc[rr][2][c2] + rAcc[rr][3][c2];
        float S = rS[rr][0] + rS[rr][1] + rS[rr][2] + rS[rr][3];
        float o = a / S;
        float m = o;
#pragma unroll
        for (int off = 8; off; off >>= 1)
            m = fmaxf(m, __shfl_xor_sync(0xffffffffu, m, off, 16));
        float ex = __expf(o - m), sum = ex;
#pragma unroll
        for (int off = 8; off; off >>= 1)
            sum += __shfl_xor_sync(0xffffffffu, sum, off, 16);
        out[(blockIdx.x * 4 + rr) * N_CLS + c2] = o - m - __logf(sum);
    }
}

// ---------------- launch ----------------------------------------------------
extern "C" void kernel_launch(void* const* d_in, const int* in_sizes, int n_in,
                              void* d_out, int out_size) {
    (void)in_sizes; (void)n_in; (void)out_size;
    const float* x       = (const float*)d_in[0];
    const float* adj     = (const float*)d_in[1];
    const float* W_heads = (const float*)d_in[2];
    const float* a_heads = (const float*)d_in[3];
    const float* W_final = (const float*)d_in[4];
    const float* a_final = (const float*)d_in[5];
    float* out = (float*)d_out;

    repack_kernel<<<64, 1024>>>(W_heads);
    gemm1_kernel<<<dim3(64, 4), 128>>>(x);
    reduce_kernel<<<1024, 256>>>(a_heads);
    attn1_kernel<<<N_NODES, 256>>>(adj, W_final, a_final);
    attn2_kernel<<<1024, 256>>>(out);
}

// round 5
// speedup vs baseline: 1.6142x; 1.0324x over previous
#include <cuda_runtime.h>
#include <cuda_bf16.h>
#include <cstdint>

#define N_NODES 4096
#define N_FEAT  1024
#define N_HID   8
#define N_HEADS 8
#define N_CLS   16
#define NCOL    64   // N_HEADS * N_HID
#define KSPLIT  8

// ---------------- scratch (static device globals: allocation-free) ----------
__device__ float g_part[KSPLIT][N_NODES * NCOL];   // split-K partials
__device__ float g_Wh  [N_NODES * NCOL];
__device__ float g_fs1 [N_NODES * N_HEADS];
__device__ float g_fd1 [N_NODES * N_HEADS];
__device__ float g_Wh2 [N_NODES * N_CLS];
__device__ float g_fs2 [N_NODES];
__device__ float g_fd2 [N_NODES];
__device__ unsigned short g_nbr[(size_t)N_NODES * N_NODES];
__device__ int   g_cnt [N_NODES];

// ---------------- f32x2 packed FMA helpers ----------------------------------
__device__ __forceinline__ void ffma2(unsigned long long& d,
                                      unsigned long long a,
                                      unsigned long long b) {
    asm("fma.rn.f32x2 %0, %1, %2, %0;" : "+l"(d) : "l"(a), "l"(b));
}
__device__ __forceinline__ unsigned long long dup2(float x) {
    unsigned long long r; unsigned xi = __float_as_uint(x);
    asm("mov.b64 %0, {%1, %1};" : "=l"(r) : "r"(xi));
    return r;
}
__device__ __forceinline__ float lo2(unsigned long long v) {
    unsigned a, b; asm("mov.b64 {%0, %1}, %2;" : "=r"(a), "=r"(b) : "l"(v));
    return __uint_as_float(a);
}
__device__ __forceinline__ float hi2(unsigned long long v) {
    unsigned a, b; asm("mov.b64 {%0, %1}, %2;" : "=r"(a), "=r"(b) : "l"(v));
    return __uint_as_float(b);
}

// ---------------- kernel 1: GEMM1, split-K x8, double-buffered ---------------
// grid (64, 8): 64 row-tiles of 64 rows, 8 K-splits of 128. 128 threads.
// W loaded directly from W_heads: cols c4..c4+3 (c4 % 4 == 0) of the packed
// [k][64] matrix are contiguous in W_heads ([h][k][f], f block of 4).
__global__ __launch_bounds__(128) void gemm1_kernel(const float* __restrict__ X,
                                                    const float* __restrict__ Wheads) {
    __shared__ float Xs[2][32][72];   // [k][row], padded
    __shared__ float Ws[2][32][64];

    const int tid = threadIdx.x;
    const int tx = tid & 15;
    const int ty = tid >> 4;
    const int row0 = blockIdx.x * 64;
    const int kbase = blockIdx.y * 128;

    float4 xr[4], wr[4];

    auto ldg_tile = [&](int k0) {
#pragma unroll
        for (int i = 0; i < 4; i++) {
            int f = tid + i * 128;
            int xrow = f >> 3, kq = f & 7;
            xr[i] = *(const float4*)(X + (size_t)(row0 + xrow) * N_FEAT + k0 + kq * 4);
            int kr = f >> 4, c4 = (f & 15) * 4;
            // W_heads[h][k][f] with h = c4>>3, f0 = c4&7 (f0 in {0,4})
            wr[i] = *(const float4*)(Wheads + ((c4 >> 3) << 13) + ((k0 + kr) << 3) + (c4 & 7));
        }
    };
    auto sts_tile = [&](int b) {
#pragma unroll
        for (int i = 0; i < 4; i++) {
            int f = tid + i * 128;
            int xrow = f >> 3, kq = f & 7;
            Xs[b][kq * 4 + 0][xrow] = xr[i].x;
            Xs[b][kq * 4 + 1][xrow] = xr[i].y;
            Xs[b][kq * 4 + 2][xrow] = xr[i].z;
            Xs[b][kq * 4 + 3][xrow] = xr[i].w;
            int kr = f >> 4, c4 = (f & 15) * 4;
            *(float4*)&Ws[b][kr][c4] = wr[i];
        }
    };

    unsigned long long acc[8][2];
#pragma unroll
    for (int r = 0; r < 8; r++) { acc[r][0] = 0ull; acc[r][1] = 0ull; }

    ldg_tile(kbase);
    sts_tile(0);
    __syncthreads();

#pragma unroll 1
    for (int t = 0; t < 4; t++) {
        int cur = t & 1;
        if (t < 3) ldg_tile(kbase + (t + 1) * 32);
#pragma unroll
        for (int k = 0; k < 32; k++) {
            float4 xlo = *(const float4*)&Xs[cur][k][ty * 8];
            float4 xhi = *(const float4*)&Xs[cur][k][ty * 8 + 4];
            ulonglong2 wv = *(const ulonglong2*)&Ws[cur][k][tx * 4];
            unsigned long long xv;
            xv = dup2(xlo.x); ffma2(acc[0][0], xv, wv.x); ffma2(acc[0][1], xv, wv.y);
            xv = dup2(xlo.y); ffma2(acc[1][0], xv, wv.x); ffma2(acc[1][1], xv, wv.y);
            xv = dup2(xlo.z); ffma2(acc[2][0], xv, wv.x); ffma2(acc[2][1], xv, wv.y);
            xv = dup2(xlo.w); ffma2(acc[3][0], xv, wv.x); ffma2(acc[3][1], xv, wv.y);
            xv = dup2(xhi.x); ffma2(acc[4][0], xv, wv.x); ffma2(acc[4][1], xv, wv.y);
            xv = dup2(xhi.y); ffma2(acc[5][0], xv, wv.x); ffma2(acc[5][1], xv, wv.y);
            xv = dup2(xhi.z); ffma2(acc[6][0], xv, wv.x); ffma2(acc[6][1], xv, wv.y);
            xv = dup2(xhi.w); ffma2(acc[7][0], xv, wv.x); ffma2(acc[7][1], xv, wv.y);
        }
        if (t < 3) {
            __syncthreads();
            sts_tile(cur ^ 1);
            __syncthreads();
        }
    }

    float* dst = g_part[blockIdx.y];
#pragma unroll
    for (int r = 0; r < 8; r++) {
        int row = row0 + ty * 8 + r;
        *(float4*)(dst + (size_t)row * NCOL + tx * 4) =
            make_float4(lo2(acc[r][0]), hi2(acc[r][0]), lo2(acc[r][1]), hi2(acc[r][1]));
    }
}

// ---------------- kernel 2: split-K reduce + per-head feature dots -----------
__global__ __launch_bounds__(256) void reduce_kernel(const float* __restrict__ a_heads) {
    __shared__ float sAsrc[64], sAdst[64];
    int tid = threadIdx.x;
    if (tid < 64) {
        int h = tid >> 3, f = tid & 7;
        sAsrc[tid] = a_heads[h * 16 + f];
        sAdst[tid] = a_heads[h * 16 + 8 + f];
    }
    __syncthreads();
    int idx = blockIdx.x * 256 + tid;
    int c = idx & 63;
    float s = 0.f;
#pragma unroll
    for (int q = 0; q < KSPLIT; q++) s += g_part[q][idx];
    g_Wh[idx] = s;
    float fsp = s * sAsrc[c], fdp = s * sAdst[c];
#pragma unroll
    for (int off = 1; off < 8; off <<= 1) {
        fsp += __shfl_xor_sync(0xffffffffu, fsp, off);
        fdp += __shfl_xor_sync(0xffffffffu, fdp, off);
    }
    if ((c & 7) == 0) {
        int row = idx >> 6, h = c >> 3;
        g_fs1[row * N_HEADS + h] = fsp;
        g_fd1[row * N_HEADS + h] = fdp;
    }
}

// ---------------- kernel 3: nbr build + layer-1 attn + elu + W2 + dots ------
// 512 threads per row-block: 8 edge-groups x 64 cols.
__global__ __launch_bounds__(512) void attn1_kernel(const float* __restrict__ adj,
                                                    const float* __restrict__ Wf,
                                                    const float* __restrict__ af) {
    __shared__ unsigned short sList[4096];
    __shared__ int sWs[17];
    __shared__ float sfs[8];
    __shared__ float sH[64];
    __shared__ float sWf[64 * 16];
    __shared__ float sAf[32];
    __shared__ float sAcc[8][64];
    __shared__ float sS[8][8];
    __shared__ float sPart[8][16];

    int row = blockIdx.x, tid = threadIdx.x;
    if (tid < 8) sfs[tid] = g_fs1[row * N_HEADS + tid];
    for (int t = tid; t < 1024; t += 512) sWf[t] = Wf[t];
    if (tid < 32) sAf[tid] = af[tid];

    // ---- phase 1: adjacency scan + deterministic compaction (8 elems/thread)
    const float* arow = adj + (size_t)row * N_NODES;
    int base = tid * 8;
    unsigned mask = 0;
    {
        float4 v0 = *(const float4*)(arow + base);
        float4 v1 = *(const float4*)(arow + base + 4);
        if (v0.x > 0.f) mask |= 1u;
        if (v0.y > 0.f) mask |= 2u;
        if (v0.z > 0.f) mask |= 4u;
        if (v0.w > 0.f) mask |= 8u;
        if (v1.x > 0.f) mask |= 16u;
        if (v1.y > 0.f) mask |= 32u;
        if (v1.z > 0.f) mask |= 64u;
        if (v1.w > 0.f) mask |= 128u;
    }
    int c = __popc(mask);
    int lane = tid & 31, wid = tid >> 5;
    int v = c;
#pragma unroll
    for (int off = 1; off < 32; off <<= 1) {
        int n = __shfl_up_sync(0xffffffffu, v, off);
        if (lane >= off) v += n;
    }
    if (lane == 31) sWs[wid] = v;
    __syncthreads();
    if (tid == 0) {
        int a = 0;
#pragma unroll
        for (int w = 0; w < 16; w++) { int t = sWs[w]; sWs[w] = a; a += t; }
        sWs[16] = a;
    }
    __syncthreads();
    int pos = sWs[wid] + v - c;
    unsigned m = mask;
    while (m) {
        int b = __ffs(m) - 1;
        m &= m - 1;
        sList[pos++] = (unsigned short)(base + b);
    }
    __syncthreads();
    int cnt = sWs[16];
    if (tid == 0) g_cnt[row] = cnt;
    for (int t = tid; t < cnt; t += 512)
        g_nbr[(size_t)row * N_NODES + t] = sList[t];

    // ---- phase 2: attention; 8 edge-groups x 64 cols, 2-way unrolled
    {
        int g = tid >> 6, l = tid & 63;
        int h = l >> 3;
        float fsa = sfs[h];
        float acc = 0.f, ssum = 0.f;
        int e = g;
        for (; e + 8 < cnt; e += 16) {
            int j0 = sList[e], j1 = sList[e + 8];
            float fd0 = __ldg(&g_fd1[j0 * N_HEADS + h]);
            float fd1 = __ldg(&g_fd1[j1 * N_HEADS + h]);
            float w0v = __ldg(&g_Wh[(size_t)j0 * NCOL + l]);
            float w1v = __ldg(&g_Wh[(size_t)j1 * NCOL + l]);
            float e0 = fsa + fd0; e0 = e0 > 0.f ? e0 : 0.2f * e0;
            float e1 = fsa + fd1; e1 = e1 > 0.f ? e1 : 0.2f * e1;
            float wg0 = __expf(e0), wg1 = __expf(e1);
            acc += wg0 * w0v;
            acc += wg1 * w1v;
            if ((l & 7) == 0) { ssum += wg0; ssum += wg1; }
        }
        for (; e < cnt; e += 8) {
            int j = sList[e];
            float ev = fsa + __ldg(&g_fd1[j * N_HEADS + h]);
            ev = ev > 0.f ? ev : 0.2f * ev;
            float wgt = __expf(ev);
            acc += wgt * __ldg(&g_Wh[(size_t)j * NCOL + l]);
            if ((l & 7) == 0) ssum += wgt;
        }
        sAcc[g][l] = acc;
        if ((l & 7) == 0) sS[g][h] = ssum;
    }
    __syncthreads();
    if (tid < 64) {
        int l = tid, h = l >> 3;
        float a = 0.f, S = 0.f;
#pragma unroll
        for (int q = 0; q < 8; q++) { a += sAcc[q][l]; S += sS[q][h]; }
        float h1 = a / S;
        sH[l] = h1 > 0.f ? h1 : __expf(h1) - 1.f;   // elu fused
    }
    __syncthreads();

    // ---- phase 3: layer-2 projection (64x16) + feature dots
    if (tid < 128) {
        int kg = tid >> 4, cc = tid & 15;
        float p = 0.f;
#pragma unroll
        for (int q = 0; q < 8; q++) {
            int kk = kg * 8 + q;
            p += sH[kk] * sWf[kk * 16 + cc];
        }
        sPart[kg][cc] = p;
    }
    __syncthreads();
    if (tid < 16) {
        float acc2 = 0.f;
#pragma unroll
        for (int q = 0; q < 8; q++) acc2 += sPart[q][tid];
        g_Wh2[row * N_CLS + tid] = acc2;
        float fsp = acc2 * sAf[tid], fdp = acc2 * sAf[16 + tid];
#pragma unroll
        for (int off = 1; off < 16; off <<= 1) {
            fsp += __shfl_xor_sync(0x0000ffffu, fsp, off);
            fdp += __shfl_xor_sync(0x0000ffffu, fdp, off);
        }
        if (tid == 0) { g_fs2[row] = fsp; g_fd2[row] = fdp; }
    }
}

// ---------------- kernel 4: layer-2 attention + log_softmax -----------------
// 2 rows/block, 128 threads per row = 8 edge-subgroups x 16 classes
__global__ __launch_bounds__(256) void attn2_kernel(float* __restrict__ out) {
    __shared__ float rAcc[2][8][16];
    __shared__ float rS[2][8];

    int tid = threadIdx.x;
    int rl = tid >> 7;               // row-local 0..1
    int t128 = tid & 127;
    int sub = t128 >> 4, cc = t128 & 15;
    int row = blockIdx.x * 2 + rl;
    int cnt = g_cnt[row];
    float fs = g_fs2[row];
    const unsigned short* nb = g_nbr + (size_t)row * N_NODES;
    float acc = 0.f, s = 0.f;
    for (int e = sub; e < cnt; e += 8) {
        int j = nb[e];
        float ev = fs + __ldg(&g_fd2[j]);
        ev = ev > 0.f ? ev : 0.2f * ev;
        float w = __expf(ev);
        acc += w * __ldg(&g_Wh2[j * N_CLS + cc]);
        if (cc == 0) s += w;
    }
    rAcc[rl][sub][cc] = acc;
    if (cc == 0) rS[rl][sub] = s;
    __syncthreads();

    if (tid < 32) {
        int rr = tid >> 4, c2 = tid & 15;
        float a = 0.f, S = 0.f;
#pragma unroll
        for (int q = 0; q < 8; q++) { a += rAcc[rr][q][c2]; S += rS[rr][q]; }
        float o = a / S;
        float mx = o;
#pragma unroll
        for (int off = 8; off; off >>= 1)
            mx = fmaxf(mx, __shfl_xor_sync(0xffffffffu, mx, off, 16));
        float ex = __expf(o - mx), sum = ex;
#pragma unroll
        for (int off = 8; off; off >>= 1)
            sum += __shfl_xor_sync(0xffffffffu, sum, off, 16);
        out[(blockIdx.x * 2 + rr) * N_CLS + c2] = o - mx - __logf(sum);
    }
}

// ---------------- launch ----------------------------------------------------
extern "C" void kernel_launch(void* const* d_in, const int* in_sizes, int n_in,
                              void* d_out, int out_size) {
    (void)in_sizes; (void)n_in; (void)out_size;
    const float* x       = (const float*)d_in[0];
    const float* adj     = (const float*)d_in[1];
    const float* W_heads = (const float*)d_in[2];
    const float* a_heads = (const float*)d_in[3];
    const float* W_final = (const float*)d_in[4];
    const float* a_final = (const float*)d_in[5];
    float* out = (float*)d_out;

    gemm1_kernel<<<dim3(64, KSPLIT), 128>>>(x, W_heads);
    reduce_kernel<<<1024, 256>>>(a_heads);
    attn1_kernel<<<N_NODES, 512>>>(adj, W_final, a_final);
    attn2_kernel<<<2048, 256>>>(out);
}

// round 6
// speedup vs baseline: 1.6772x; 1.0390x over previous
#include <cuda_runtime.h>
#include <cuda_bf16.h>
#include <cstdint>

#define N_NODES 4096
#define N_FEAT  1024
#define N_HID   8
#define N_HEADS 8
#define N_CLS   16
#define NCOL    64   // N_HEADS * N_HID
#define KSPLIT  8
#define NGEMMB  512  // 64 row-tiles x 8 k-splits

// ---------------- scratch (static device globals: allocation-free) ----------
__device__ float g_part[KSPLIT][N_NODES * NCOL];
__device__ float g_Wh  [N_NODES * NCOL];
__device__ float g_fs1 [N_NODES * N_HEADS];
__device__ float g_fd1 [N_NODES * N_HEADS];
__device__ float g_Wh2 [N_NODES * N_CLS];
__device__ float g_fs2 [N_NODES];
__device__ float g_fd2 [N_NODES];
__device__ unsigned short g_nbr[(size_t)N_NODES * N_NODES];
__device__ int   g_cnt [N_NODES];

// ---------------- f32x2 packed FMA helpers ----------------------------------
__device__ __forceinline__ void ffma2(unsigned long long& d,
                                      unsigned long long a,
                                      unsigned long long b) {
    asm("fma.rn.f32x2 %0, %1, %2, %0;" : "+l"(d) : "l"(a), "l"(b));
}
__device__ __forceinline__ unsigned long long dup2(float x) {
    unsigned long long r; unsigned xi = __float_as_uint(x);
    asm("mov.b64 %0, {%1, %1};" : "=l"(r) : "r"(xi));
    return r;
}
__device__ __forceinline__ float lo2(unsigned long long v) {
    unsigned a, b; asm("mov.b64 {%0, %1}, %2;" : "=r"(a), "=r"(b) : "l"(v));
    return __uint_as_float(a);
}
__device__ __forceinline__ float hi2(unsigned long long v) {
    unsigned a, b; asm("mov.b64 {%0, %1}, %2;" : "=r"(a), "=r"(b) : "l"(v));
    return __uint_as_float(b);
}

// ---------------- kernel 1: fused GEMM1 (blocks 0..511) + nbr build ---------
struct GemmS { float Xs[2][32][72]; float Ws[2][32][64]; };
struct NbrS  { unsigned short sList[4096]; int sWs[9]; };
union SmemU  { GemmS g; NbrS n; };

__global__ __launch_bounds__(256) void fused_kernel(const float* __restrict__ X,
                                                    const float* __restrict__ Wheads,
                                                    const float* __restrict__ adj) {
    __shared__ SmemU smem;
    const int tid = threadIdx.x;
    const int bid = blockIdx.x;

    if (bid < NGEMMB) {
        // ======== GEMM part: BM=64, BN=64, BK=32; thread tile 4 rows x 4 cols
        const int rt = bid & 63, ks = bid >> 6;
        const int row0 = rt * 64, kbase = ks * 128;
        const int tx = tid & 15, ty = tid >> 4;

        float4 xr[2], wr[2];
        auto ldg_tile = [&](int k0) {
#pragma unroll
            for (int i = 0; i < 2; i++) {
                int f = tid + i * 256;
                int xrow = f >> 3, kq = f & 7;
                xr[i] = *(const float4*)(X + (size_t)(row0 + xrow) * N_FEAT + k0 + kq * 4);
                int kr = f >> 4, c4 = (f & 15) * 4;
                wr[i] = *(const float4*)(Wheads + ((c4 >> 3) << 13) + ((k0 + kr) << 3) + (c4 & 7));
            }
        };
        auto sts_tile = [&](int b) {
#pragma unroll
            for (int i = 0; i < 2; i++) {
                int f = tid + i * 256;
                int xrow = f >> 3, kq = f & 7;
                smem.g.Xs[b][kq * 4 + 0][xrow] = xr[i].x;
                smem.g.Xs[b][kq * 4 + 1][xrow] = xr[i].y;
                smem.g.Xs[b][kq * 4 + 2][xrow] = xr[i].z;
                smem.g.Xs[b][kq * 4 + 3][xrow] = xr[i].w;
                int kr = f >> 4, c4 = (f & 15) * 4;
                *(float4*)&smem.g.Ws[b][kr][c4] = wr[i];
            }
        };

        unsigned long long acc[4][2];
#pragma unroll
        for (int r = 0; r < 4; r++) { acc[r][0] = 0ull; acc[r][1] = 0ull; }

        ldg_tile(kbase);
        sts_tile(0);
        __syncthreads();

#pragma unroll 1
        for (int t = 0; t < 4; t++) {
            int cur = t & 1;
            if (t < 3) ldg_tile(kbase + (t + 1) * 32);
#pragma unroll
            for (int k = 0; k < 32; k++) {
                float4 xv4 = *(const float4*)&smem.g.Xs[cur][k][ty * 4];
                ulonglong2 wv = *(const ulonglong2*)&smem.g.Ws[cur][k][tx * 4];
                unsigned long long xv;
                xv = dup2(xv4.x); ffma2(acc[0][0], xv, wv.x); ffma2(acc[0][1], xv, wv.y);
                xv = dup2(xv4.y); ffma2(acc[1][0], xv, wv.x); ffma2(acc[1][1], xv, wv.y);
                xv = dup2(xv4.z); ffma2(acc[2][0], xv, wv.x); ffma2(acc[2][1], xv, wv.y);
                xv = dup2(xv4.w); ffma2(acc[3][0], xv, wv.x); ffma2(acc[3][1], xv, wv.y);
            }
            if (t < 3) {
                __syncthreads();
                sts_tile(cur ^ 1);
                __syncthreads();
            }
        }

        float* dst = g_part[ks];
#pragma unroll
        for (int r = 0; r < 4; r++) {
            int row = row0 + ty * 4 + r;
            *(float4*)(dst + (size_t)row * NCOL + tx * 4) =
                make_float4(lo2(acc[r][0]), hi2(acc[r][0]), lo2(acc[r][1]), hi2(acc[r][1]));
        }
    } else {
        // ======== nbr part: one block per row, 16 adj elems per thread
        int row = bid - NGEMMB;
        const float* arow = adj + (size_t)row * N_NODES;
        int base = tid * 16;
        unsigned mask = 0;
#pragma unroll
        for (int q = 0; q < 4; q++) {
            float4 v = *(const float4*)(arow + base + q * 4);
            if (v.x > 0.f) mask |= 1u << (q * 4 + 0);
            if (v.y > 0.f) mask |= 1u << (q * 4 + 1);
            if (v.z > 0.f) mask |= 1u << (q * 4 + 2);
            if (v.w > 0.f) mask |= 1u << (q * 4 + 3);
        }
        int c = __popc(mask);
        int lane = tid & 31, wid = tid >> 5;
        int v = c;
#pragma unroll
        for (int off = 1; off < 32; off <<= 1) {
            int n = __shfl_up_sync(0xffffffffu, v, off);
            if (lane >= off) v += n;
        }
        if (lane == 31) smem.n.sWs[wid] = v;
        __syncthreads();
        if (tid == 0) {
            int a = 0;
#pragma unroll
            for (int w = 0; w < 8; w++) { int t = smem.n.sWs[w]; smem.n.sWs[w] = a; a += t; }
            smem.n.sWs[8] = a;
        }
        __syncthreads();
        int pos = smem.n.sWs[wid] + v - c;
        unsigned m = mask;
        while (m) {
            int b = __ffs(m) - 1;
            m &= m - 1;
            smem.n.sList[pos++] = (unsigned short)(base + b);
        }
        __syncthreads();
        int cnt = smem.n.sWs[8];
        if (tid == 0) g_cnt[row] = cnt;
        for (int t = tid; t < cnt; t += 256)
            g_nbr[(size_t)row * N_NODES + t] = smem.n.sList[t];
    }
}

// ---------------- kernel 2: split-K reduce + per-head feature dots -----------
__global__ __launch_bounds__(256) void reduce_kernel(const float* __restrict__ a_heads) {
    __shared__ float sAsrc[64], sAdst[64];
    int tid = threadIdx.x;
    if (tid < 64) {
        int h = tid >> 3, f = tid & 7;
        sAsrc[tid] = a_heads[h * 16 + f];
        sAdst[tid] = a_heads[h * 16 + 8 + f];
    }
    __syncthreads();
    int idx = blockIdx.x * 256 + tid;
    int c = idx & 63;
    float s = 0.f;
#pragma unroll
    for (int q = 0; q < KSPLIT; q++) s += g_part[q][idx];
    g_Wh[idx] = s;
    float fsp = s * sAsrc[c], fdp = s * sAdst[c];
#pragma unroll
    for (int off = 1; off < 8; off <<= 1) {
        fsp += __shfl_xor_sync(0xffffffffu, fsp, off);
        fdp += __shfl_xor_sync(0xffffffffu, fdp, off);
    }
    if ((c & 7) == 0) {
        int row = idx >> 6, h = c >> 3;
        g_fs1[row * N_HEADS + h] = fsp;
        g_fd1[row * N_HEADS + h] = fdp;
    }
}

// ---------------- kernel 3: layer-1 gather attention + elu + W2 + dots ------
// 256 threads: 4 edge-groups x 64 cols. Neighbor list staged to smem.
__global__ __launch_bounds__(256) void attnA_kernel(const float* __restrict__ Wf,
                                                    const float* __restrict__ af) {
    __shared__ unsigned short sList[4096];
    __shared__ float sfs[8];
    __shared__ float sH[64];
    __shared__ float sWf[64 * 16];
    __shared__ float sAf[32];
    __shared__ float sAcc[4][64];
    __shared__ float sS[4][8];
    __shared__ float sPart[8][16];

    int row = blockIdx.x, tid = threadIdx.x;
    int cnt = g_cnt[row];
    if (tid < 8) sfs[tid] = g_fs1[row * N_HEADS + tid];
    for (int t = tid; t < 1024; t += 256) sWf[t] = Wf[t];
    if (tid < 32) sAf[tid] = af[tid];
    for (int t = tid; t < cnt; t += 256)
        sList[t] = g_nbr[(size_t)row * N_NODES + t];
    __syncthreads();

    // phase 1: gather attention, 4 groups x 64 cols, 2-way unrolled (stride 8)
    {
        int g = tid >> 6, l = tid & 63;
        int h = l >> 3;
        float fsa = sfs[h];
        float acc = 0.f, ssum = 0.f;
        int e = g;
        for (; e + 4 < cnt; e += 8) {
            int j0 = sList[e], j1 = sList[e + 4];
            float fd0 = __ldg(&g_fd1[j0 * N_HEADS + h]);
            float fd1 = __ldg(&g_fd1[j1 * N_HEADS + h]);
            float w0v = __ldg(&g_Wh[(size_t)j0 * NCOL + l]);
            float w1v = __ldg(&g_Wh[(size_t)j1 * NCOL + l]);
            float e0 = fsa + fd0; e0 = e0 > 0.f ? e0 : 0.2f * e0;
            float e1 = fsa + fd1; e1 = e1 > 0.f ? e1 : 0.2f * e1;
            float wg0 = __expf(e0), wg1 = __expf(e1);
            acc += wg0 * w0v;
            acc += wg1 * w1v;
            if ((l & 7) == 0) { ssum += wg0; ssum += wg1; }
        }
        for (; e < cnt; e += 4) {
            int j = sList[e];
            float ev = fsa + __ldg(&g_fd1[j * N_HEADS + h]);
            ev = ev > 0.f ? ev : 0.2f * ev;
            float wgt = __expf(ev);
            acc += wgt * __ldg(&g_Wh[(size_t)j * NCOL + l]);
            if ((l & 7) == 0) ssum += wgt;
        }
        sAcc[g][l] = acc;
        if ((l & 7) == 0) sS[g][h] = ssum;
    }
    __syncthreads();
    if (tid < 64) {
        int l = tid, h = l >> 3;
        float a = sAcc[0][l] + sAcc[1][l] + sAcc[2][l] + sAcc[3][l];
        float S = sS[0][h] + sS[1][h] + sS[2][h] + sS[3][h];
        float h1 = a / S;
        sH[l] = h1 > 0.f ? h1 : __expf(h1) - 1.f;   // elu fused
    }
    __syncthreads();

    // phase 2: 64x16 projection + feature dots
    if (tid < 128) {
        int kg = tid >> 4, cc = tid & 15;
        float p = 0.f;
#pragma unroll
        for (int q = 0; q < 8; q++) {
            int kk = kg * 8 + q;
            p += sH[kk] * sWf[kk * 16 + cc];
        }
        sPart[kg][cc] = p;
    }
    __syncthreads();
    if (tid < 16) {
        float acc2 = 0.f;
#pragma unroll
        for (int q = 0; q < 8; q++) acc2 += sPart[q][tid];
        g_Wh2[row * N_CLS + tid] = acc2;
        float fsp = acc2 * sAf[tid], fdp = acc2 * sAf[16 + tid];
#pragma unroll
        for (int off = 1; off < 16; off <<= 1) {
            fsp += __shfl_xor_sync(0x0000ffffu, fsp, off);
            fdp += __shfl_xor_sync(0x0000ffffu, fdp, off);
        }
        if (tid == 0) { g_fs2[row] = fsp; g_fd2[row] = fdp; }
    }
}

// ---------------- kernel 4: layer-2 attention + log_softmax -----------------
// 1 row/block, 256 threads = 16 edge-subgroups x 16 classes
__global__ __launch_bounds__(256) void attn2_kernel(float* __restrict__ out) {
    __shared__ float rAcc[16][16];
    __shared__ float rS[16];

    int tid = threadIdx.x;
    int sub = tid >> 4, cc = tid & 15;
    int row = blockIdx.x;
    int cnt = g_cnt[row];
    float fs = g_fs2[row];
    const unsigned short* nb = g_nbr + (size_t)row * N_NODES;
    float acc = 0.f, s = 0.f;
    for (int e = sub; e < cnt; e += 16) {
        int j = nb[e];
        float ev = fs + __ldg(&g_fd2[j]);
        ev = ev > 0.f ? ev : 0.2f * ev;
        float w = __expf(ev);
        acc += w * __ldg(&g_Wh2[j * N_CLS + cc]);
        if (cc == 0) s += w;
    }
    rAcc[sub][cc] = acc;
    if (cc == 0) rS[sub] = s;
    __syncthreads();

    if (tid < 16) {
        float a = 0.f, S = 0.f;
#pragma unroll
        for (int q = 0; q < 16; q++) { a += rAcc[q][tid]; S += rS[q]; }
        float o = a / S;
        float mx = o;
#pragma unroll
        for (int off = 8; off; off >>= 1)
            mx = fmaxf(mx, __shfl_xor_sync(0x0000ffffu, mx, off, 16));
        float ex = __expf(o - mx), sum = ex;
#pragma unroll
        for (int off = 8; off; off >>= 1)
            sum += __shfl_xor_sync(0x0000ffffu, sum, off, 16);
        out[row * N_CLS + tid] = o - mx - __logf(sum);
    }
}

// ---------------- launch ----------------------------------------------------
extern "C" void kernel_launch(void* const* d_in, const int* in_sizes, int n_in,
                              void* d_out, int out_size) {
    (void)in_sizes; (void)n_in; (void)out_size;
    const float* x       = (const float*)d_in[0];
    const float* adj     = (const float*)d_in[1];
    const float* W_heads = (const float*)d_in[2];
    const float* a_heads = (const float*)d_in[3];
    const float* W_final = (const float*)d_in[4];
    const float* a_final = (const float*)d_in[5];
    float* out = (float*)d_out;

    fused_kernel<<<NGEMMB + N_NODES, 256>>>(x, W_heads, adj);
    reduce_kernel<<<1024, 256>>>(a_heads);
    attnA_kernel<<<N_NODES, 256>>>(W_final, a_final);
    attn2_kernel<<<N_NODES, 256>>>(out);
}